// round 17
// baseline (speedup 1.0000x reference)
#include <cuda_runtime.h>

#define FULL 0xffffffffu

static constexpr int B_ = 64;
static constexpr int S_ = 12;
static constexpr int N_ = 207;
static constexpr int F_ = 2;
static constexpr int NCIRC = B_ * N_;       // 13248
static constexpr int CPB = 4;               // circuits per 128-thread block (1/warp)
static constexpr float PI_F = 3.14159265358979323846f;

// One circuit per WARP: lanes [0,16) = re component, [16,32) = im.
// g = lane & 15. Flat j (8 bits) = (g << 4) | r.
// qubit -> j-bit: q1->7 q3->6 q5->5 q7->4 (lane g bits 3,2,1,0)
//                 q0->3 q2->2 q4->1 q6->0 (reg r bits 3,2,1,0)

__device__ __forceinline__ float shx(float v, int m) { return __shfl_xor_sync(FULL, v, m); }

// ---- fused conv pair, one qubit on lane bit LBIT, one on reg bit PB.
// Coefficients pre-arranged in shared: T2[2a] = {u00,u01,u02,u03}, T2[2a+1] = {u10..u13}.
template<int LBIT, int PB>
__device__ __forceinline__ void conv_mx(float (&st)[16], const float4* __restrict__ T2, int lane) {
    constexpr int Lm = 1 << LBIT, mb = 1 << PB;
    const int a = (lane >> LBIT) & 1;
    const float4 ua = T2[2 * a];
    const float4 ub = T2[2 * a + 1];
    #pragma unroll
    for (int r0 = 0; r0 < 16; ++r0) if (!(r0 & mb)) {
        const int r1 = r0 | mb;
        float p0 = shx(st[r0], Lm), p1 = shx(st[r1], Lm);
        float o0 = st[r0], o1 = st[r1];
        st[r0] = fmaf(ua.x, o0, fmaf(ua.y, o1, fmaf(ua.z, p0, ua.w * p1)));
        st[r1] = fmaf(ub.x, o0, fmaf(ub.y, o1, fmaf(ub.z, p0, ub.w * p1)));
    }
}

__global__ __launch_bounds__(128)
void qcnn_kernel(const float* __restrict__ x, const float* __restrict__ adj,
                 const float* __restrict__ w_proj, const float* __restrict__ b_proj,
                 const float* __restrict__ qp,
                 const float* __restrict__ w1, const float* __restrict__ b1,
                 const float* __restrict__ w2, const float* __restrict__ b2,
                 const float* __restrict__ w3, const float* __restrict__ b3,
                 float* __restrict__ out) {
    __shared__ alignas(16) float UMX[14][2][8];    // all gates mx: [gate][laneBit a][8 coefs]
    __shared__ float poolc[4], pools[4];           // FULL-angle cos/sin of pool RYs
    __shared__ alignas(16) float w1s[512];         // w1 natural [64][8]
    __shared__ float4 w2p4[32 * 17];               // w2 rows padded to 68 floats
    __shared__ float4 h1buf4[CPB * 17];
    __shared__ float b1s[64], b2s[32], w3s[32];
    __shared__ float b3s;

    const int tid = threadIdx.x;

    // ---- build fused conv matrices U = C2 * G2 * C1 * G1 ----
    if (tid < 14) {
        const int layer = tid / 7, pi = tid - 7 * layer;
        const int base = layer * 28 + pi * 4;
        float c0, s0, c1, s1, c2, s2, c3, s3;
        sincosf(0.5f * qp[base + 0], &s0, &c0);
        sincosf(0.5f * qp[base + 1], &s1, &c1);
        sincosf(0.5f * qp[base + 2], &s2, &c2);
        sincosf(0.5f * qp[base + 3], &s3, &c3);
        float R0[2][2] = {{c0, -s0}, {s0, c0}};
        float R1[2][2] = {{c1, -s1}, {s1, c1}};
        float R2m[2][2] = {{c2, -s2}, {s2, c2}};
        float R3[2][2] = {{c3, -s3}, {s3, c3}};
        float A[4][4], G2m[4][4], Bm[4][4], Cm[4][4];
        #pragma unroll
        for (int ap = 0; ap < 2; ++ap)
        #pragma unroll
        for (int bp = 0; bp < 2; ++bp)
        #pragma unroll
        for (int aq = 0; aq < 2; ++aq)
        #pragma unroll
        for (int bq = 0; bq < 2; ++bq) {
            A[2 * ap + bp][2 * aq + bq]   = R0[ap][aq] * R1[bp][bq];
            G2m[2 * ap + bp][2 * aq + bq] = R2m[ap][aq] * R3[bp][bq];
        }
        const int sig1[4] = {0, 1, 3, 2};
        const int sig2[4] = {0, 3, 2, 1};
        #pragma unroll
        for (int xr = 0; xr < 4; ++xr)
            #pragma unroll
            for (int m = 0; m < 4; ++m) Bm[xr][m] = A[sig1[xr]][m];
        #pragma unroll
        for (int xr = 0; xr < 4; ++xr)
            #pragma unroll
            for (int m = 0; m < 4; ++m) {
                float acc = 0.f;
                #pragma unroll
                for (int y = 0; y < 4; ++y) acc = fmaf(G2m[xr][y], Bm[y][m], acc);
                Cm[xr][m] = acc;
            }
        float Uf[16];
        #pragma unroll
        for (int xr = 0; xr < 4; ++xr)
            #pragma unroll
            for (int m = 0; m < 4; ++m) Uf[xr * 4 + m] = Cm[sig2[xr]][m];
        // All gates are mixed. Pairs 0..3 = first group: reg qubit FIRST (lq1=false).
        // Pairs 4..6 = second group: lane qubit FIRST (lq1=true).
        const bool lq1 = (pi >= 4);
        #pragma unroll
        for (int a = 0; a < 2; ++a) {
            int r0, r1, d0, d1;
            if (lq1) { r0 = 2 * a; r1 = 2 * a + 1; d0 = 2 * (a ^ 1); d1 = d0 + 1; }
            else     { r0 = a;     r1 = 2 + a;     d0 = a ^ 1;       d1 = 2 + (a ^ 1); }
            float* dst = &UMX[tid][a][0];
            dst[0] = Uf[r0 * 4 + r0]; dst[1] = Uf[r0 * 4 + r1];
            dst[2] = Uf[r0 * 4 + d0]; dst[3] = Uf[r0 * 4 + d1];
            dst[4] = Uf[r1 * 4 + r0]; dst[5] = Uf[r1 * 4 + r1];
            dst[6] = Uf[r1 * 4 + d0]; dst[7] = Uf[r1 * 4 + d1];
        }
    }
    if (tid >= 16 && tid < 20) {
        float s, c;
        sincosf(qp[56 + 2 * (tid - 16)], &s, &c);   // FULL angle (fused pooling)
        poolc[tid - 16] = c; pools[tid - 16] = s;
    }
    for (int i = tid; i < 512; i += 128) w1s[i] = w1[i];
    for (int i = tid; i < 2048; i += 128) {
        int row = i >> 6, j = i & 63;
        ((float*)w2p4)[row * 68 + j] = w2[i];
    }
    if (tid < 64) b1s[tid] = b1[tid];
    if (tid >= 64 && tid < 96) b2s[tid - 64] = b2[tid - 64];
    if (tid >= 96 && tid < 128) w3s[tid - 96] = w3[tid - 96];
    if (tid == 20) b3s = b3[0];
    __syncthreads();

    const int wid = tid >> 5;
    const int lane = tid & 31;
    const int comp = lane >> 4;               // 0 = re half, 1 = im half
    const int g = lane & 15;
    const int cir = blockIdx.x * CPB + wid;
    const int b = cir / N_;
    const int n = cir - b * N_;

    // ---- angle projection: lanes 0..7 patterns; all lanes compute q = lane&7 ----
    float av;
    {
        const int q = lane & 7;
        av = b_proj[q];
        const float* wrow = w_proj + q * (S_ * F_);
        const float* xb = x + (size_t)b * (S_ * N_ * F_) + n * F_;
        #pragma unroll
        for (int s = 0; s < S_; ++s) {
            float2 xv = *(const float2*)(xb + s * (N_ * F_));
            av = fmaf(wrow[2 * s], xv.x, av);
            av = fmaf(wrow[2 * s + 1], xv.y, av);
        }
        av = fminf(fmaxf(av, -PI_F), PI_F);
    }
    float sv, cv;
    __sincosf(0.5f * av, &sv, &cv);
    float ch[8], sh[8];
    #pragma unroll
    for (int q = 0; q < 8; ++q) {
        ch[q] = __shfl_sync(FULL, cv, q);
        sh[q] = __shfl_sync(FULL, sv, q);
    }

    // ---- graph CNOT mask ----
    const int c = n & 7;
    const int pcq = (0x40516273u >> (4 * c)) & 0xF;    // posOf[c]
    int cond = (lane < 8) && (adj[c * N_ + lane] > 0.f) && (lane != c);
    const unsigned bal = __ballot_sync(FULL, cond);
    const unsigned mask8 = bal & 0xFFu;
    constexpr int posOf[8] = {3, 7, 2, 6, 1, 5, 0, 4};
    int M = 0;
    #pragma unroll
    for (int t = 0; t < 8; ++t) M |= (int)((mask8 >> t) & 1u) << posOf[t];
    const int glm = (M >> 4) & 15;
    const int MR = M & 15;
    // bcmask bit r = control bit of flat index (g<<4)|r
    unsigned bcmask = (pcq == 0) ? 0xAAAAu : (pcq == 1) ? 0xCCCCu :
                      (pcq == 2) ? 0xF0F0u : 0xFF00u;
    if (pcq >= 4) bcmask = ((g >> (pcq - 4)) & 1) ? 0xFFFFu : 0u;

    // ---- build product state DIRECTLY PERMUTED by the graph CNOTs ----
    // lane bits: b1q=q1, b3q=q3, b5q=q5, b7q=q7
    const int b1q = (g >> 3) & 1, b3q = (g >> 2) & 1, b5q = (g >> 1) & 1, b7q = g & 1;
    const int gp = g ^ glm;
    const int p1q = (gp >> 3) & 1, p3q = (gp >> 2) & 1, p5q = (gp >> 1) & 1, p7q = gp & 1;

    const float magL0 = (b1q ? sh[1] : ch[1]) * (b3q ? sh[3] : ch[3])
                      * (b5q ? sh[5] : ch[5]) * (b7q ? sh[7] : ch[7]);
    const float magL1 = (p1q ? sh[1] : ch[1]) * (p3q ? sh[3] : ch[3])
                      * (p5q ? sh[5] : ch[5]) * (p7q ? sh[7] : ch[7]);
    // lane phase E_L = u1*u3:  u1 = ch5 + i*s1, u3 = ch7 + i*s3
    const float s1 = b1q ? sh[5] : -sh[5];
    const float s3 = b3q ? sh[7] : -sh[7];
    const float ELr = fmaf(ch[5], ch[7], -s1 * s3);
    const float ELi = fmaf(ch[5], s3, s1 * ch[7]);
    const float sp1 = p1q ? sh[5] : -sh[5];
    const float sp3 = p3q ? sh[7] : -sh[7];
    const float EPr = fmaf(ch[5], ch[7], -sp1 * sp3);
    const float EPi = fmaf(ch[5], sp3, sp1 * ch[7]);

    // A0/A1 over k = (q0bit<<1)|q2bit : reg phase UR[k] = u0*u2 and q0,q2 mags
    float A0[4], A1[4];
    #pragma unroll
    for (int k = 0; k < 4; ++k) {
        const float s0 = (k & 2) ? sh[4] : -sh[4];
        const float s2v = (k & 1) ? sh[6] : -sh[6];
        const float URr = fmaf(ch[4], ch[6], -s0 * s2v);
        const float URi = fmaf(ch[4], s2v, s0 * ch[6]);
        const float mg = ((k & 2) ? sh[0] : ch[0]) * ((k & 1) ? sh[2] : ch[2]);
        const float cr0 = fmaf(ELr, URr, -ELi * URi);
        const float ci0 = fmaf(ELr, URi, ELi * URr);
        const float cr1 = fmaf(EPr, URr, -EPi * URi);
        const float ci1 = fmaf(EPr, URi, EPi * URr);
        A0[k] = magL0 * mg * (comp ? ci0 : cr0);
        A1[k] = magL1 * mg * (comp ? ci1 : cr1);
    }
    // permute A1 by reg-XOR high bits, m by low bits
    const int Mk = (MR >> 2) & 3, Ml = MR & 3;
    float Ap[4];
    {
        float ta[4];
        #pragma unroll
        for (int k = 0; k < 4; ++k) ta[k] = (Mk & 1) ? A1[k ^ 1] : A1[k];
        #pragma unroll
        for (int k = 0; k < 4; ++k) Ap[k] = (Mk & 2) ? ta[k ^ 2] : ta[k];
    }
    float m0[4], mp[4];
    m0[0] = ch[4] * ch[6]; m0[1] = ch[4] * sh[6];
    m0[2] = sh[4] * ch[6]; m0[3] = sh[4] * sh[6];
    {
        float tm[4];
        #pragma unroll
        for (int l = 0; l < 4; ++l) tm[l] = (Ml & 1) ? m0[l ^ 1] : m0[l];
        #pragma unroll
        for (int l = 0; l < 4; ++l) mp[l] = (Ml & 2) ? tm[l ^ 2] : tm[l];
    }
    float st[16];
    #pragma unroll
    for (int k = 0; k < 4; ++k)
        #pragma unroll
        for (int l = 0; l < 4; ++l) {
            const int r = 4 * k + l;
            const bool bc = (bcmask >> r) & 1u;
            st[r] = (bc ? Ap[k] : A0[k]) * (bc ? mp[l] : m0[l]);
        }

    // ---- 2 conv layers: ALL gates mixed (one lane + one reg qubit) ----
    #pragma unroll
    for (int l = 0; l < 2; ++l) {
        conv_mx<3, 3>(st, (const float4*)UMX[l * 7 + 0], lane);   // (q0,q1)
        conv_mx<2, 2>(st, (const float4*)UMX[l * 7 + 1], lane);   // (q2,q3)
        conv_mx<1, 1>(st, (const float4*)UMX[l * 7 + 2], lane);   // (q4,q5)
        conv_mx<0, 0>(st, (const float4*)UMX[l * 7 + 3], lane);   // (q6,q7)
        conv_mx<3, 2>(st, (const float4*)UMX[l * 7 + 4], lane);   // (q1,q2)
        conv_mx<2, 1>(st, (const float4*)UMX[l * 7 + 5], lane);   // (q3,q4)
        conv_mx<1, 0>(st, (const float4*)UMX[l * 7 + 6], lane);   // (q5,q6)
    }

    // ---- measurement with POOLING FUSED IN (pooled qubits all on reg bits) ----
    float x0 = 0.f, x2 = 0.f, x4 = 0.f, x6 = 0.f;
    #pragma unroll
    for (int r = 0; r < 16; ++r) {
        if (!(r & 8)) x0 = fmaf(st[r], st[r | 8], x0);   // q0 pairs
        if (!(r & 4)) x2 = fmaf(st[r], st[r | 4], x2);   // q2 pairs
        if (!(r & 2)) x4 = fmaf(st[r], st[r | 2], x4);   // q4 pairs
        if (!(r & 1)) x6 = fmaf(st[r], st[r | 1], x6);   // q6 pairs
    }
    // Walsh tree over st[16] (r bits: 3=q0, 2=q2, 1=q4, 0=q6)
    float s0w[8], e6 = 0.f;
    #pragma unroll
    for (int k = 0; k < 8; ++k) {
        float pe = st[2 * k] * st[2 * k];
        float po = st[2 * k + 1] * st[2 * k + 1];
        s0w[k] = pe + po;
        e6 += pe;
    }
    float s1w[4], e4 = 0.f;
    #pragma unroll
    for (int m = 0; m < 4; ++m) { s1w[m] = s0w[2 * m] + s0w[2 * m + 1]; e4 += s0w[2 * m]; }
    const float e2 = s1w[0] + s1w[2];
    const float s2a = s1w[0] + s1w[1], s2b = s1w[2] + s1w[3];
    const float tot = s2a + s2b;
    const float z0r = s2a - s2b;
    const float z2r = fmaf(2.f, e2, -tot);
    const float z4r = fmaf(2.f, e4, -tot);
    const float z6r = fmaf(2.f, e6, -tot);

    float z[8];
    z[0] = fmaf(poolc[0], z0r, -2.f * pools[0] * x0);
    z[2] = fmaf(poolc[1], z2r, -2.f * pools[1] * x2);
    z[4] = fmaf(poolc[2], z4r, -2.f * pools[2] * x4);
    z[6] = fmaf(poolc[3], z6r, -2.f * pools[3] * x6);
    z[1] = b1q ? -tot : tot;
    z[3] = b3q ? -tot : tot;
    z[5] = b5q ? -tot : tot;
    z[7] = b7q ? -tot : tot;

    // ---- reduce-scatter over 16 lanes, then combine re/im + duplicate halves ----
    float zg;
    {
        float v[4];
        #pragma unroll
        for (int j = 0; j < 4; ++j) {
            float keep = b1q ? z[j + 4] : z[j];
            float send = b1q ? z[j] : z[j + 4];
            v[j] = keep + shx(send, 8);
        }
        float u0 = (b3q ? v[2] : v[0]) + shx(b3q ? v[0] : v[2], 4);
        float u1 = (b3q ? v[3] : v[1]) + shx(b3q ? v[1] : v[3], 4);
        zg = (b5q ? u1 : u0) + shx(b5q ? u0 : u1, 2);
        zg += shx(zg, 1);       // fold q7-bit duplicates
        zg += shx(zg, 16);      // combine re + im
    }
    // lane (w<<1) now holds Z[w]; gather full z8
    float z8[8];
    #pragma unroll
    for (int w = 0; w < 8; ++w)
        z8[w] = __shfl_sync(FULL, zg, w << 1);

    // ---- MLP head: 8 -> 64 -> 32 -> 1, all 32 lanes work ----
    // h1: this lane computes rows 2*lane, 2*lane+1
    float h1a, h1b;
    {
        const int row = 2 * lane;
        float4 wa = *(const float4*)(w1s + row * 8);
        float4 wb = *(const float4*)(w1s + row * 8 + 4);
        float acc = b1s[row];
        acc = fmaf(wa.x, z8[0], acc); acc = fmaf(wa.y, z8[1], acc);
        acc = fmaf(wa.z, z8[2], acc); acc = fmaf(wa.w, z8[3], acc);
        acc = fmaf(wb.x, z8[4], acc); acc = fmaf(wb.y, z8[5], acc);
        acc = fmaf(wb.z, z8[6], acc); acc = fmaf(wb.w, z8[7], acc);
        h1a = fmaxf(acc, 0.f);
        wa = *(const float4*)(w1s + row * 8 + 8);
        wb = *(const float4*)(w1s + row * 8 + 12);
        acc = b1s[row + 1];
        acc = fmaf(wa.x, z8[0], acc); acc = fmaf(wa.y, z8[1], acc);
        acc = fmaf(wa.z, z8[2], acc); acc = fmaf(wa.w, z8[3], acc);
        acc = fmaf(wb.x, z8[4], acc); acc = fmaf(wb.y, z8[5], acc);
        acc = fmaf(wb.z, z8[6], acc); acc = fmaf(wb.w, z8[7], acc);
        h1b = fmaxf(acc, 0.f);
    }
    *(float2*)((float*)h1buf4 + wid * 68 + 2 * lane) = make_float2(h1a, h1b);
    __syncwarp();

    // h2: this lane computes row = lane
    float acc2 = b2s[lane];
    const float4* h1p = h1buf4 + wid * 17;
    #pragma unroll
    for (int j4 = 0; j4 < 16; ++j4) {
        float4 h = h1p[j4];
        float4 w = w2p4[lane * 17 + j4];
        acc2 = fmaf(w.x, h.x, fmaf(w.y, h.y, fmaf(w.z, h.z, fmaf(w.w, h.w, acc2))));
    }
    float o = w3s[lane] * fmaxf(acc2, 0.f);
    o += shx(o, 1); o += shx(o, 2); o += shx(o, 4); o += shx(o, 8); o += shx(o, 16);
    if (lane == 0) out[cir] = o + b3s;
}

extern "C" void kernel_launch(void* const* d_in, const int* in_sizes, int n_in,
                              void* d_out, int out_size) {
    const float* x      = (const float*)d_in[0];
    const float* adj    = (const float*)d_in[1];
    const float* w_proj = (const float*)d_in[2];
    const float* b_proj = (const float*)d_in[3];
    const float* qp     = (const float*)d_in[4];
    const float* w1     = (const float*)d_in[5];
    const float* b1     = (const float*)d_in[6];
    const float* w2     = (const float*)d_in[7];
    const float* b2     = (const float*)d_in[8];
    const float* w3     = (const float*)d_in[9];
    const float* b3     = (const float*)d_in[10];
    float* out = (float*)d_out;

    const int blocks = NCIRC / CPB;   // 3312
    qcnn_kernel<<<blocks, 128>>>(x, adj, w_proj, b_proj, qp,
                                 w1, b1, w2, b2, w3, b3, out);
}